// round 1
// baseline (speedup 1.0000x reference)
#include <cuda_runtime.h>
#include <cstdint>
#include <math.h>

#define CS     8      // cluster size (CTAs per batch, split along rows)
#define ROWS   24     // rows per CTA = 192/8
#define PITCH  196    // row pitch in floats: 2 zero cols + 192 data + 2 zero cols
#define LROWS  26     // ROWS + 2 halo rows
#define NG     192
#define TSTEPS 256
#define KPT    12     // rows per thread (2 row-groups of 192 threads)

__device__ __forceinline__ uint32_t s2u(const void* p) {
    return (uint32_t)__cvta_generic_to_shared((void*)p);
}
__device__ __forceinline__ uint32_t mapa_u32(uint32_t a, uint32_t r) {
    uint32_t d;
    asm("mapa.shared::cluster.u32 %0, %1, %2;" : "=r"(d) : "r"(a), "r"(r));
    return d;
}
__device__ __forceinline__ void st_cluster_f32(uint32_t a, float v) {
    asm volatile("st.shared::cluster.f32 [%0], %1;" :: "r"(a), "f"(v) : "memory");
}
__device__ __forceinline__ void cluster_sync_() {
    asm volatile("barrier.cluster.arrive.aligned;" ::: "memory");
    asm volatile("barrier.cluster.wait.aligned;" ::: "memory");
}

// PML 1D profile: v[k] = 3*(k/20)^4 ; b[i] = v[20-i] for i<=20, v[i-171] for i>=171
__device__ __forceinline__ float pml1(int i) {
    int d;
    if (i <= 20)           d = 20 - i;
    else if (i >= NG - 21) d = i - (NG - 21);
    else return 0.0f;
    double t = (double)d * 0.05;
    double t2 = t * t;
    return (float)(3.0 * t2 * t2);
}

__global__ void __cluster_dims__(CS, 1, 1) __launch_bounds__(384, 1)
wave_kernel(const float* __restrict__ x, const float* __restrict__ rho,
            float* __restrict__ out)
{
    __shared__ float bufs[2][LROWS * PITCH];  // double-buffered y field (with halos/pads)
    __shared__ float xs[TSTEPS];              // per-batch source series
    __shared__ float pbuf[3];                 // probe accumulators (rank 6 only)

    const int tid   = threadIdx.x;
    const int col   = tid % NG;       // 0..191
    const int rgrp  = tid / NG;       // 0 or 1
    const int rank  = blockIdx.x % CS;
    const int batch = blockIdx.x / CS;

    // Zero both buffers (halos + pad columns included) and stage x.
    for (int i = tid; i < 2 * LROWS * PITCH; i += 384) (&bufs[0][0])[i] = 0.f;
    for (int i = tid; i < TSTEPS; i += 384) xs[i] = x[batch * TSTEPS + i];

    // ---- Per-cell constants (registers): Q, R ----
    const float HM2 = (float)(1.0 / (2.01 * 2.01));
    float Qc[KPT], Rc[KPT], y2[KPT];
#pragma unroll
    for (int k = 0; k < KPT; ++k) {
        const int g = rank * ROWS + rgrp * KPT + k;   // global row
        float cc = rho[g * NG + col];
        float nn = (g > 0)      ? rho[(g - 1) * NG + col] : 0.f;
        float ss = (g < NG - 1) ? rho[(g + 1) * NG + col] : 0.f;
        float ww = (col > 0)    ? rho[g * NG + col - 1]   : 0.f;
        float ee = (col < NG-1) ? rho[g * NG + col + 1]   : 0.f;
        float lpf = 0.5f * cc + 0.125f * nn + 0.125f * ss + 0.125f * ww + 0.125f * ee;
        // proj(x) = (tanh(50) + tanh(100(x-0.5))) / (2 tanh(50)); tanhf(50)==1
        float pr = (1.0f + tanhf(100.0f * (lpf - 0.5f))) * 0.5f;
        float c  = 1.0f - 0.1f * pr;           // C0 + (C1-C0)*pr
        float bx = pml1(g), by = pml1(col);
        float b  = sqrtf(bx * bx + by * by);
        float A1 = 1.0f / (1.0f + 0.5f * b);
        Qc[k] = A1 * (1.0f - 0.5f * b);        // A1*A3 ; note A1*A2 = 1 + Qc
        Rc[k] = A1 * (c * c) * HM2;            // A1*c^2/H^2
        y2[k] = 0.f;
    }

    const int base = rgrp * KPT + 1;   // first local data row for this thread
    const float* p0 = &bufs[0][base * PITCH + col + 2];
    const float* p1 = &bufs[1][base * PITCH + col + 2];

    // DSMEM halo-push addresses (top row -> prev CTA's bottom halo, etc.)
    const bool doUp = (rank > 0)      && (rgrp == 0);
    const bool doDn = (rank < CS - 1) && (rgrp == 1);
    uint32_t upA[2] = {0, 0}, dnA[2] = {0, 0};
    if (doUp) {
        upA[0] = mapa_u32(s2u(&bufs[0][(ROWS + 1) * PITCH + col + 2]), (uint32_t)(rank - 1));
        upA[1] = mapa_u32(s2u(&bufs[1][(ROWS + 1) * PITCH + col + 2]), (uint32_t)(rank - 1));
    }
    if (doDn) {
        dnA[0] = mapa_u32(s2u(&bufs[0][col + 2]), (uint32_t)(rank + 1));
        dnA[1] = mapa_u32(s2u(&bufs[1][col + 2]), (uint32_t)(rank + 1));
    }

    // Source (40,96): rank 1, local row 17 -> rgrp 1, k == 4.
    // Probes (160,{48,96,144}): rank 6, local row 17 -> rgrp 1, k == 4.
    const bool isSrc = (rank == 1) && (rgrp == 1) && (col == 96);
    const bool isPrb = (rank == 6) && (rgrp == 1) &&
                       ((col == 48) | (col == 96) | (col == 144));
    float pacc = 0.f;

    cluster_sync_();  // zeros + setup visible cluster-wide

    for (int t = 0; t < TSTEPS; ++t) {
        const int wb = (t & 1) ^ 1;
        const float* rp = (t & 1) ? p1 : p0;
        float* wp = const_cast<float*>((t & 1) ? p0 : p1);

        float n = rp[-PITCH];   // north of first row (halo or intra-CTA row)
        float c = rp[0];
#pragma unroll
        for (int k = 0; k < KPT; ++k) {
            float s  = rp[(k + 1) * PITCH];
            float wv = rp[k * PITCH - 1];
            float ev = rp[k * PITCH + 1];
            float lap = (n + s + wv + ev) - 4.0f * c;
            float yn = c + Qc[k] * (c - y2[k]) + Rc[k] * lap;
            if (k == 4) {
                if (isSrc) yn += xs[t];
            }
            wp[k * PITCH] = yn;
            if (k == 4) {
                if (isPrb) pacc = fmaf(yn, yn, pacc);
            }
            if (k == 0)       { if (doUp) st_cluster_f32(upA[wb], yn); }
            if (k == KPT - 1) { if (doDn) st_cluster_f32(dnA[wb], yn); }
            y2[k] = c;
            n = c;
            c = s;
        }
        cluster_sync_();  // writes (incl. DSMEM halo pushes) visible before next read
    }

    // Output: I[p] / sum_p I[p], per batch (written by rank-6 CTA of each cluster)
    if (isPrb) pbuf[(col - 48) / 48] = pacc;
    __syncthreads();
    if (rank == 6 && tid == 0) {
        float a = pbuf[0], b = pbuf[1], cc = pbuf[2];
        float sum = a + b + cc;
        out[batch * 3 + 0] = a / sum;
        out[batch * 3 + 1] = b / sum;
        out[batch * 3 + 2] = cc / sum;
    }
}

extern "C" void kernel_launch(void* const* d_in, const int* in_sizes, int n_in,
                              void* d_out, int out_size)
{
    (void)in_sizes; (void)n_in; (void)out_size;
    const float* x   = (const float*)d_in[0];   // (4,256) f32
    const float* rho = (const float*)d_in[1];   // (192,192) f32
    float* out = (float*)d_out;                 // (4,3) f32
    wave_kernel<<<dim3(CS * 4), dim3(384)>>>(x, rho, out);
}